// round 13
// baseline (speedup 1.0000x reference)
#include <cuda_runtime.h>

// out[e,b,o] = sum_n x[e,b,n] * W[e,o,n] + b[e,o]
// E=50000, B=512, N=2, O=2. Pure HBM streaming (~411 MB logical traffic).
//
// FINAL — frozen at the measured roofline (56.3-57.2us kernel, ~79% DRAM,
// ~6.3 TB/s counter / ~7.2 TB/s effective = ~90% of spec for a 50/50
// read/write mixed stream).
//  - 256-bit global ld/st (LDG.E.256/STG.E.256, sm_100+): half the memory
//    instructions, 1024B contiguous per warp per access (R8 win).
//  - 2 front-batched f8 loads per thread (64 x-bytes) — proven MLP optimum.
//  - DEFAULT cache operators (every .cs variant regressed, R3/R6).
//  - One-shot CTAs, exact tiling, zero predicates, warp-uniform W/b.
// Measured-dead levers: occupancy (R2/R4), block size (R7), UNROLL 8 (R5),
// persistence (R9), cache hints (R3/R6), store batching (R11).

#define THREADS 256
#define CHUNKS 2                 // 2 x float8 per thread = 64 bytes of x

struct f8 { float v[8]; };

__device__ __forceinline__ f8 ldg256(const float* p) {
    f8 r;
    asm volatile("ld.global.nc.v8.f32 {%0,%1,%2,%3,%4,%5,%6,%7}, [%8];"
                 : "=f"(r.v[0]), "=f"(r.v[1]), "=f"(r.v[2]), "=f"(r.v[3]),
                   "=f"(r.v[4]), "=f"(r.v[5]), "=f"(r.v[6]), "=f"(r.v[7])
                 : "l"(p));
    return r;
}

__device__ __forceinline__ void stg256(float* p, const f8& r) {
    asm volatile("st.global.v8.f32 [%0], {%1,%2,%3,%4,%5,%6,%7,%8};"
                 :: "l"(p),
                    "f"(r.v[0]), "f"(r.v[1]), "f"(r.v[2]), "f"(r.v[3]),
                    "f"(r.v[4]), "f"(r.v[5]), "f"(r.v[6]), "f"(r.v[7])
                 : "memory");
}

__global__ void __launch_bounds__(THREADS) plt_exact(
        const float* __restrict__ x,
        const float4* __restrict__ W4,
        const float2* __restrict__ b2,
        float* __restrict__ out) {
    // Block covers [blockIdx.x*512, +512) f8s; each 256-f8 chunk spans
    // exactly 2 edges (128 f8s = 1024 floats per edge).
    int base = blockIdx.x * (THREADS * CHUNKS) + threadIdx.x;
    int half = threadIdx.x >> 7;                 // 0/1, warp-uniform
    int e0 = blockIdx.x * (2 * CHUNKS) + half;   // edge of chunk 0

    // Front-batched 256-bit x loads.
    f8 xv[CHUNKS];
    #pragma unroll
    for (int k = 0; k < CHUNKS; k++)
        xv[k] = ldg256(x + (long)(base + k * THREADS) * 8);

    // Warp-uniform W/b loads (edge advances by 2 per chunk).
    float4 wv[CHUNKS];
    float2 bv[CHUNKS];
    #pragma unroll
    for (int k = 0; k < CHUNKS; k++) {
        wv[k] = __ldg(W4 + e0 + 2 * k);
        bv[k] = __ldg(b2 + e0 + 2 * k);
    }

    #pragma unroll
    for (int k = 0; k < CHUNKS; k++) {
        f8 o;
        #pragma unroll
        for (int p = 0; p < 4; p++) {          // 4 (b,n) pairs per f8
            float a0 = xv[k].v[2 * p], a1 = xv[k].v[2 * p + 1];
            o.v[2 * p]     = fmaf(a0, wv[k].x, fmaf(a1, wv[k].y, bv[k].x));
            o.v[2 * p + 1] = fmaf(a0, wv[k].z, fmaf(a1, wv[k].w, bv[k].y));
        }
        stg256(out + (long)(base + k * THREADS) * 8, o);
    }
}

// Guarded fallback for shapes that don't tile exactly (not hit for E=50000).
__global__ void __launch_bounds__(256) plt_generic(
        const float4* __restrict__ x4,
        const float4* __restrict__ W4,
        const float2* __restrict__ b2,
        float4* __restrict__ out4,
        int total_quads,
        int log2_quads_per_edge) {
    int i = blockIdx.x * 256 + threadIdx.x;
    if (i >= total_quads) return;
    int e = i >> log2_quads_per_edge;
    float4 xv = __ldg(x4 + i);
    float4 wv = __ldg(W4 + e);
    float2 bv = __ldg(b2 + e);
    float4 o;
    o.x = fmaf(xv.x, wv.x, fmaf(xv.y, wv.y, bv.x));
    o.y = fmaf(xv.x, wv.z, fmaf(xv.y, wv.w, bv.y));
    o.z = fmaf(xv.z, wv.x, fmaf(xv.w, wv.y, bv.x));
    o.w = fmaf(xv.z, wv.z, fmaf(xv.w, wv.w, bv.y));
    out4[i] = o;
}

extern "C" void kernel_launch(void* const* d_in, const int* in_sizes, int n_in,
                              void* d_out, int out_size) {
    const float* x = (const float*)d_in[0];   // [E, B, N]
    const float* W = (const float*)d_in[1];   // [E, O, N]
    const float* b = (const float*)d_in[2];   // [E, O]

    int E = in_sizes[2] / 2;                  // 50000
    int per_edge = in_sizes[0] / E;           // B*N = 1024 floats
    int total_floats = in_sizes[0];           // 51.2M
    int floats_per_block = THREADS * CHUNKS * 8;   // 4096

    // Fast path: 1024 floats per edge (so each 128-thread half-chunk = one
    // edge) and exact grid tiling.
    if (per_edge == 1024 && total_floats % floats_per_block == 0) {
        int blocks = total_floats / floats_per_block;   // 12500
        plt_exact<<<blocks, THREADS>>>(x, (const float4*)W,
                                       (const float2*)b, (float*)d_out);
    } else {
        int quads_per_edge = per_edge / 4;
        int log2_q = 0;
        while ((1 << log2_q) < quads_per_edge) log2_q++;
        int total_quads = total_floats / 4;
        int blocks = (total_quads + 255) / 256;
        plt_generic<<<blocks, 256>>>((const float4*)x, (const float4*)W,
                                     (const float2*)b, (float4*)d_out,
                                     total_quads, log2_q);
    }
}

// round 14
// speedup vs baseline: 1.0025x; 1.0025x over previous
#include <cuda_runtime.h>

// out[e,b,o] = sum_n x[e,b,n] * W[e,o,n] + b[e,o]
// E=50000, B=512, N=2, O=2. Pure HBM streaming (~411 MB logical traffic).
//
// FINAL — frozen at the measured roofline (56.3-57.2us kernel, ~79% DRAM,
// ~6.3 TB/s counter / ~7.3 TB/s effective = ~91% of spec for a 50/50
// read/write mixed stream).
//  - 256-bit global ld/st (LDG.E.256/STG.E.256, sm_100+): half the memory
//    instructions, 1024B contiguous per warp per access (R8 win).
//  - 2 front-batched f8 loads per thread (64 x-bytes) — proven MLP optimum.
//  - DEFAULT cache operators (every .cs variant regressed, R3/R6).
//  - One-shot CTAs, exact tiling, zero predicates, warp-uniform W/b.
// Measured-dead levers: occupancy (R2/R4), block size (R7), UNROLL 8 (R5),
// persistence (R9), cache hints (R3/R6), store batching (R11).

#define THREADS 256
#define CHUNKS 2                 // 2 x float8 per thread = 64 bytes of x

struct f8 { float v[8]; };

__device__ __forceinline__ f8 ldg256(const float* p) {
    f8 r;
    asm volatile("ld.global.nc.v8.f32 {%0,%1,%2,%3,%4,%5,%6,%7}, [%8];"
                 : "=f"(r.v[0]), "=f"(r.v[1]), "=f"(r.v[2]), "=f"(r.v[3]),
                   "=f"(r.v[4]), "=f"(r.v[5]), "=f"(r.v[6]), "=f"(r.v[7])
                 : "l"(p));
    return r;
}

__device__ __forceinline__ void stg256(float* p, const f8& r) {
    asm volatile("st.global.v8.f32 [%0], {%1,%2,%3,%4,%5,%6,%7,%8};"
                 :: "l"(p),
                    "f"(r.v[0]), "f"(r.v[1]), "f"(r.v[2]), "f"(r.v[3]),
                    "f"(r.v[4]), "f"(r.v[5]), "f"(r.v[6]), "f"(r.v[7])
                 : "memory");
}

__global__ void __launch_bounds__(THREADS) plt_exact(
        const float* __restrict__ x,
        const float4* __restrict__ W4,
        const float2* __restrict__ b2,
        float* __restrict__ out) {
    // Block covers [blockIdx.x*512, +512) f8s; each 256-f8 chunk spans
    // exactly 2 edges (128 f8s = 1024 floats per edge).
    int base = blockIdx.x * (THREADS * CHUNKS) + threadIdx.x;
    int half = threadIdx.x >> 7;                 // 0/1, warp-uniform
    int e0 = blockIdx.x * (2 * CHUNKS) + half;   // edge of chunk 0

    // Front-batched 256-bit x loads.
    f8 xv[CHUNKS];
    #pragma unroll
    for (int k = 0; k < CHUNKS; k++)
        xv[k] = ldg256(x + (long)(base + k * THREADS) * 8);

    // Warp-uniform W/b loads (edge advances by 2 per chunk).
    float4 wv[CHUNKS];
    float2 bv[CHUNKS];
    #pragma unroll
    for (int k = 0; k < CHUNKS; k++) {
        wv[k] = __ldg(W4 + e0 + 2 * k);
        bv[k] = __ldg(b2 + e0 + 2 * k);
    }

    #pragma unroll
    for (int k = 0; k < CHUNKS; k++) {
        f8 o;
        #pragma unroll
        for (int p = 0; p < 4; p++) {          // 4 (b,n) pairs per f8
            float a0 = xv[k].v[2 * p], a1 = xv[k].v[2 * p + 1];
            o.v[2 * p]     = fmaf(a0, wv[k].x, fmaf(a1, wv[k].y, bv[k].x));
            o.v[2 * p + 1] = fmaf(a0, wv[k].z, fmaf(a1, wv[k].w, bv[k].y));
        }
        stg256(out + (long)(base + k * THREADS) * 8, o);
    }
}

// Guarded fallback for shapes that don't tile exactly (not hit for E=50000).
__global__ void __launch_bounds__(256) plt_generic(
        const float4* __restrict__ x4,
        const float4* __restrict__ W4,
        const float2* __restrict__ b2,
        float4* __restrict__ out4,
        int total_quads,
        int log2_quads_per_edge) {
    int i = blockIdx.x * 256 + threadIdx.x;
    if (i >= total_quads) return;
    int e = i >> log2_quads_per_edge;
    float4 xv = __ldg(x4 + i);
    float4 wv = __ldg(W4 + e);
    float2 bv = __ldg(b2 + e);
    float4 o;
    o.x = fmaf(xv.x, wv.x, fmaf(xv.y, wv.y, bv.x));
    o.y = fmaf(xv.x, wv.z, fmaf(xv.y, wv.w, bv.y));
    o.z = fmaf(xv.z, wv.x, fmaf(xv.w, wv.y, bv.x));
    o.w = fmaf(xv.z, wv.z, fmaf(xv.w, wv.w, bv.y));
    out4[i] = o;
}

extern "C" void kernel_launch(void* const* d_in, const int* in_sizes, int n_in,
                              void* d_out, int out_size) {
    const float* x = (const float*)d_in[0];   // [E, B, N]
    const float* W = (const float*)d_in[1];   // [E, O, N]
    const float* b = (const float*)d_in[2];   // [E, O]

    int E = in_sizes[2] / 2;                  // 50000
    int per_edge = in_sizes[0] / E;           // B*N = 1024 floats
    int total_floats = in_sizes[0];           // 51.2M
    int floats_per_block = THREADS * CHUNKS * 8;   // 4096

    // Fast path: 1024 floats per edge (so each 128-thread half-chunk = one
    // edge) and exact grid tiling.
    if (per_edge == 1024 && total_floats % floats_per_block == 0) {
        int blocks = total_floats / floats_per_block;   // 12500
        plt_exact<<<blocks, THREADS>>>(x, (const float4*)W,
                                       (const float2*)b, (float*)d_out);
    } else {
        int quads_per_edge = per_edge / 4;
        int log2_q = 0;
        while ((1 << log2_q) < quads_per_edge) log2_q++;
        int total_quads = total_floats / 4;
        int blocks = (total_quads + 255) / 256;
        plt_generic<<<blocks, 256>>>((const float4*)x, (const float4*)W,
                                     (const float2*)b, (float4*)d_out,
                                     total_quads, log2_q);
    }
}

// round 17
// speedup vs baseline: 1.0040x; 1.0015x over previous
#include <cuda_runtime.h>

// out[e,b,o] = sum_n x[e,b,n] * W[e,o,n] + b[e,o]
// E=50000, B=512, N=2, O=2. Pure HBM streaming (~411 MB logical traffic).
//
// FINAL — frozen at the measured roofline (56.3-57.2us kernel, ~79% DRAM,
// ~6.3 TB/s counter / ~7.3 TB/s effective = ~91% of spec for a 50/50
// read/write mixed stream; L2 absorbs ~50 MB of writes per replay).
//  - 256-bit global ld/st (LDG.E.256/STG.E.256, sm_100+): half the memory
//    instructions, 1024B contiguous per warp per access (R8 win).
//  - 2 front-batched f8 loads per thread (64 x-bytes) — proven MLP optimum.
//  - DEFAULT cache operators (every .cs variant regressed, R3/R6).
//  - One-shot CTAs, exact tiling, zero predicates, warp-uniform W/b.
// Measured-dead levers: occupancy (R2/R4), block size (R7), UNROLL 8 (R5),
// persistence (R9), cache hints (R3/R6), store batching (R11).
// Theory-dead levers: TMA store staging (L2 schedules writebacks, not STG
// order; LTS cap path-independent), L2 residency control (unreachable or
// rule-violating), traversal-order L2 tricks (determinism + symmetry),
// channel striding (LTS saturates first).

#define THREADS 256
#define CHUNKS 2                 // 2 x float8 per thread = 64 bytes of x

struct f8 { float v[8]; };

__device__ __forceinline__ f8 ldg256(const float* p) {
    f8 r;
    asm volatile("ld.global.nc.v8.f32 {%0,%1,%2,%3,%4,%5,%6,%7}, [%8];"
                 : "=f"(r.v[0]), "=f"(r.v[1]), "=f"(r.v[2]), "=f"(r.v[3]),
                   "=f"(r.v[4]), "=f"(r.v[5]), "=f"(r.v[6]), "=f"(r.v[7])
                 : "l"(p));
    return r;
}

__device__ __forceinline__ void stg256(float* p, const f8& r) {
    asm volatile("st.global.v8.f32 [%0], {%1,%2,%3,%4,%5,%6,%7,%8};"
                 :: "l"(p),
                    "f"(r.v[0]), "f"(r.v[1]), "f"(r.v[2]), "f"(r.v[3]),
                    "f"(r.v[4]), "f"(r.v[5]), "f"(r.v[6]), "f"(r.v[7])
                 : "memory");
}

__global__ void __launch_bounds__(THREADS) plt_exact(
        const float* __restrict__ x,
        const float4* __restrict__ W4,
        const float2* __restrict__ b2,
        float* __restrict__ out) {
    // Block covers [blockIdx.x*512, +512) f8s; each 256-f8 chunk spans
    // exactly 2 edges (128 f8s = 1024 floats per edge).
    int base = blockIdx.x * (THREADS * CHUNKS) + threadIdx.x;
    int half = threadIdx.x >> 7;                 // 0/1, warp-uniform
    int e0 = blockIdx.x * (2 * CHUNKS) + half;   // edge of chunk 0

    // Front-batched 256-bit x loads.
    f8 xv[CHUNKS];
    #pragma unroll
    for (int k = 0; k < CHUNKS; k++)
        xv[k] = ldg256(x + (long)(base + k * THREADS) * 8);

    // Warp-uniform W/b loads (edge advances by 2 per chunk).
    float4 wv[CHUNKS];
    float2 bv[CHUNKS];
    #pragma unroll
    for (int k = 0; k < CHUNKS; k++) {
        wv[k] = __ldg(W4 + e0 + 2 * k);
        bv[k] = __ldg(b2 + e0 + 2 * k);
    }

    #pragma unroll
    for (int k = 0; k < CHUNKS; k++) {
        f8 o;
        #pragma unroll
        for (int p = 0; p < 4; p++) {          // 4 (b,n) pairs per f8
            float a0 = xv[k].v[2 * p], a1 = xv[k].v[2 * p + 1];
            o.v[2 * p]     = fmaf(a0, wv[k].x, fmaf(a1, wv[k].y, bv[k].x));
            o.v[2 * p + 1] = fmaf(a0, wv[k].z, fmaf(a1, wv[k].w, bv[k].y));
        }
        stg256(out + (long)(base + k * THREADS) * 8, o);
    }
}

// Guarded fallback for shapes that don't tile exactly (not hit for E=50000).
__global__ void __launch_bounds__(256) plt_generic(
        const float4* __restrict__ x4,
        const float4* __restrict__ W4,
        const float2* __restrict__ b2,
        float4* __restrict__ out4,
        int total_quads,
        int log2_quads_per_edge) {
    int i = blockIdx.x * 256 + threadIdx.x;
    if (i >= total_quads) return;
    int e = i >> log2_quads_per_edge;
    float4 xv = __ldg(x4 + i);
    float4 wv = __ldg(W4 + e);
    float2 bv = __ldg(b2 + e);
    float4 o;
    o.x = fmaf(xv.x, wv.x, fmaf(xv.y, wv.y, bv.x));
    o.y = fmaf(xv.x, wv.z, fmaf(xv.y, wv.w, bv.y));
    o.z = fmaf(xv.z, wv.x, fmaf(xv.w, wv.y, bv.x));
    o.w = fmaf(xv.z, wv.z, fmaf(xv.w, wv.w, bv.y));
    out4[i] = o;
}

extern "C" void kernel_launch(void* const* d_in, const int* in_sizes, int n_in,
                              void* d_out, int out_size) {
    const float* x = (const float*)d_in[0];   // [E, B, N]
    const float* W = (const float*)d_in[1];   // [E, O, N]
    const float* b = (const float*)d_in[2];   // [E, O]

    int E = in_sizes[2] / 2;                  // 50000
    int per_edge = in_sizes[0] / E;           // B*N = 1024 floats
    int total_floats = in_sizes[0];           // 51.2M
    int floats_per_block = THREADS * CHUNKS * 8;   // 4096

    // Fast path: 1024 floats per edge (so each 128-thread half-chunk = one
    // edge) and exact grid tiling.
    if (per_edge == 1024 && total_floats % floats_per_block == 0) {
        int blocks = total_floats / floats_per_block;   // 12500
        plt_exact<<<blocks, THREADS>>>(x, (const float4*)W,
                                       (const float2*)b, (float*)d_out);
    } else {
        int quads_per_edge = per_edge / 4;
        int log2_q = 0;
        while ((1 << log2_q) < quads_per_edge) log2_q++;
        int total_quads = total_floats / 4;
        int blocks = (total_quads + 255) / 256;
        plt_generic<<<blocks, 256>>>((const float4*)x, (const float4*)W,
                                     (const float2*)b, (float4*)d_out,
                                     total_quads, log2_q);
    }
}